// round 14
// baseline (speedup 1.0000x reference)
#include <cuda_runtime.h>
#include <cuda_bf16.h>
#include <cuda_fp16.h>
#include <cstdint>

#define NN 50000        // capacity: nodes
#define EE 800000       // capacity: edges
#define HID 128
#define MAXDEG 96       // bucket capacity; P(deg>96) < 1e-30 for this graph

// ---------------- scratch (static __device__, no allocation) ----------------
__device__ __half g_hx[NN * 128];    // fp16 copy of h   (aggregation input L1)
__device__ __half g_h2x[NN * 128];   // fp16 copy of h2  (aggregation input L2)
__device__ __nv_bfloat16 g_Hh[NN * 128],  g_Hl[NN * 128];    // h   split
__device__ __nv_bfloat16 g_H2h[NN * 128], g_H2l[NN * 128];   // h2  split
__device__ __nv_bfloat16 g_Agh[NN * 128], g_Agl[NN * 128];   // agg split
__device__ int   g_cnt[NN];          // per-node edge count
__device__ int   g_csr2[NN * MAXDEG];
__device__ __nv_bfloat16 g_Bhi1[128 * 256];   // B[o][k] = {W1_l | W1_r} hi
__device__ __nv_bfloat16 g_Blo1[128 * 256];   // residual lo
__device__ __nv_bfloat16 g_Bhi2[128 * 256];
__device__ __nv_bfloat16 g_Blo2[128 * 256];
__device__ int   g_E;        // true edge count (device-detected)
__device__ int   g_e64;      // edge_index is int64
__device__ int   g_x64;      // x is int64

// ---------------- PTX helpers (all plain, no arch-'a' gating) ----------------
__device__ __forceinline__ void mma16816(float* d, const uint32_t* a, const uint32_t* b) {
    asm volatile(
        "mma.sync.aligned.m16n8k16.row.col.f32.bf16.bf16.f32 "
        "{%0,%1,%2,%3}, {%4,%5,%6,%7}, {%8,%9}, {%0,%1,%2,%3};"
        : "+f"(d[0]), "+f"(d[1]), "+f"(d[2]), "+f"(d[3])
        : "r"(a[0]), "r"(a[1]), "r"(a[2]), "r"(a[3]), "r"(b[0]), "r"(b[1]));
}
__device__ __forceinline__ void ldsm4(uint32_t* r, uint32_t addr) {
    asm volatile("ldmatrix.sync.aligned.m8n8.x4.shared.b16 {%0,%1,%2,%3}, [%4];"
        : "=r"(r[0]), "=r"(r[1]), "=r"(r[2]), "=r"(r[3]) : "r"(addr));
}
__device__ __forceinline__ uint32_t smem_u32(const void* p) {
    uint32_t a;
    asm("{ .reg .u64 t; cvta.to.shared.u64 t, %1; cvt.u32.u64 %0, t; }" : "=r"(a) : "l"(p));
    return a;
}
__device__ __forceinline__ void cpa16(uint32_t s, const void* g) {
    asm volatile("cp.async.ca.shared.global [%0], [%1], 16;" :: "r"(s), "l"(g));
}
__device__ __forceinline__ void cpa_commit() {
    asm volatile("cp.async.commit_group;" ::: "memory");
}
template <int NWait>
__device__ __forceinline__ void cpa_wait() {
    asm volatile("cp.async.wait_group %0;" :: "n"(NWait) : "memory");
}
__device__ __forceinline__ void bf16split(float v, __nv_bfloat16& hi, __nv_bfloat16& lo) {
    hi = __float2bfloat16(v);
    lo = __float2bfloat16(v - __bfloat162float(hi));
}

// ---------------- init: zero cnt, thread0 does dtype/count detect ----------
__global__ void init_kernel(const int* __restrict__ ei, long long eiW,
                            const int* __restrict__ x, long long xW,
                            int elemMode, int n) {
    int i = blockIdx.x * blockDim.x + threadIdx.x;
    if (i < n) g_cnt[i] = 0;
    if (blockIdx.x == 0 && threadIdx.x == 0) {
        int e64 = 1;
        for (long long j = 1; j < 256 && j < eiW; j += 2)
            if (ei[j] != 0) { e64 = 0; break; }
        int x64 = 1;
        for (long long j = 1; j < 256 && j < xW; j += 2)
            if (x[j] != 0) { x64 = 0; break; }
        long long E;
        if (elemMode) E = eiW / 2;
        else          E = e64 ? eiW / 4 : eiW / 2;
        if (E > EE) E = EE;
        if (E < 0)  E = 0;
        g_E = (int)E;
        g_e64 = e64;
        g_x64 = x64;
    }
}

// ---------------- fused build: bucket CSR + gather(+split) + weight prep ----
__global__ void build_kernel(const int* __restrict__ ei,
                             const int* __restrict__ x, const float* __restrict__ emb,
                             int n, long long embRows,
                             const float* __restrict__ W1l, const float* __restrict__ W1r,
                             const float* __restrict__ W2l, const float* __restrict__ W2r,
                             int edgeBlocks) {
    if (blockIdx.x < edgeBlocks) {
        int i = blockIdx.x * blockDim.x + threadIdx.x;
        int E = g_E;
        if (i >= E) return;
        int e64 = g_e64;
        long long dstBase = e64 ? 2LL * E : (long long)E;
        int sv = e64 ? ei[2LL * i] : ei[i];
        int dv = e64 ? ei[dstBase + 2LL * i] : ei[dstBase + i];
        sv = max(0, min(sv, n - 1));
        dv = max(0, min(dv, n - 1));
        int pos = atomicAdd(&g_cnt[dv], 1);
        if (pos < MAXDEG) g_csr2[dv * MAXDEG + pos] = sv;
    } else {
        int idx = (blockIdx.x - edgeBlocks) * blockDim.x + threadIdx.x;
        int gWork = n * 32;
        if (idx < gWork) {
            int node = idx >> 5;
            int c4 = (idx & 31) * 4;
            long long row = g_x64 ? (long long)x[2LL * node] : (long long)x[node];
            if (row < 0) row = 0;
            if (row >= embRows) row = embRows - 1;
            float4 v = *(const float4*)(emb + row * 128 + c4);
            long long o = (long long)node * 128 + c4;
            __half2* hp = (__half2*)(g_hx + o);
            hp[0] = __floats2half2_rn(v.x, v.y);
            hp[1] = __floats2half2_rn(v.z, v.w);
            __nv_bfloat16 h0, l0, h1, l1, h2, l2, h3, l3;
            bf16split(v.x, h0, l0); bf16split(v.y, h1, l1);
            bf16split(v.z, h2, l2); bf16split(v.w, h3, l3);
            __nv_bfloat162 ph0; ph0.x = h0; ph0.y = h1;
            __nv_bfloat162 ph1; ph1.x = h2; ph1.y = h3;
            __nv_bfloat162 pl0; pl0.x = l0; pl0.y = l1;
            __nv_bfloat162 pl1; pl1.x = l2; pl1.y = l3;
            *(__nv_bfloat162*)(g_Hh + o)     = ph0;
            *(__nv_bfloat162*)(g_Hh + o + 2) = ph1;
            *(__nv_bfloat162*)(g_Hl + o)     = pl0;
            *(__nv_bfloat162*)(g_Hl + o + 2) = pl1;
        } else {
            int w = idx - gWork;
            if (w >= 2 * 128 * 256) return;
            int which = w >> 15;
            int rem = w & 32767;
            int o = rem >> 8;
            int k = rem & 255;
            const float* Wl = which ? W2l : W1l;
            const float* Wr = which ? W2r : W1r;
            float v = (k < 128) ? Wl[o * 128 + k] : Wr[o * 128 + (k - 128)];
            __nv_bfloat16 hi, lo;
            bf16split(v, hi, lo);
            (which ? g_Bhi2 : g_Bhi1)[o * 256 + k] = hi;
            (which ? g_Blo2 : g_Blo1)[o * 256 + k] = lo;
        }
    }
}

// ---------------- mean aggregation: 2 nodes per warp, writes bf16 split -----
__global__ void aggregate_kernel(const __half* __restrict__ hx,
                                 const int* __restrict__ ei, int n) {
    int warp = (blockIdx.x * blockDim.x + threadIdx.x) >> 5;
    int lane = threadIdx.x & 31;
    int node = warp * 2 + (lane >> 4);
    int sub = lane & 15;
    if (node >= n) return;
    int deg = g_cnt[node];
    float a0 = 0.f, a1 = 0.f, a2 = 0.f, a3 = 0.f;
    float a4 = 0.f, a5 = 0.f, a6 = 0.f, a7 = 0.f;
    if (deg <= MAXDEG) {
        const int* bucket = g_csr2 + node * MAXDEG;
        for (int e = 0; e < deg; e++) {
            int s = __ldg(&bucket[e]);
            uint4 u = *(const uint4*)(hx + (long long)s * 128 + sub * 8);
            __half2* hp = (__half2*)&u;
            float2 f0 = __half22float2(hp[0]);
            float2 f1 = __half22float2(hp[1]);
            float2 f2 = __half22float2(hp[2]);
            float2 f3 = __half22float2(hp[3]);
            a0 += f0.x; a1 += f0.y; a2 += f1.x; a3 += f1.y;
            a4 += f2.x; a5 += f2.y; a6 += f3.x; a7 += f3.y;
        }
    } else {
        int E = g_E;
        int e64 = g_e64;
        long long dstBase = e64 ? 2LL * E : (long long)E;
        for (int i = 0; i < E; i++) {
            int dv = e64 ? ei[dstBase + 2LL * i] : ei[dstBase + i];
            if (dv != node) continue;
            int sv = e64 ? ei[2LL * i] : ei[i];
            sv = max(0, min(sv, n - 1));
            uint4 u = *(const uint4*)(hx + (long long)sv * 128 + sub * 8);
            __half2* hp = (__half2*)&u;
            float2 f0 = __half22float2(hp[0]);
            float2 f1 = __half22float2(hp[1]);
            float2 f2 = __half22float2(hp[2]);
            float2 f3 = __half22float2(hp[3]);
            a0 += f0.x; a1 += f0.y; a2 += f1.x; a3 += f1.y;
            a4 += f2.x; a5 += f2.y; a6 += f3.x; a7 += f3.y;
        }
    }
    float inv = 1.0f / fmaxf((float)deg, 1.0f);
    float r[8] = {a0 * inv, a1 * inv, a2 * inv, a3 * inv,
                  a4 * inv, a5 * inv, a6 * inv, a7 * inv};
    __nv_bfloat16 hi8[8], lo8[8];
#pragma unroll
    for (int j = 0; j < 8; j++) bf16split(r[j], hi8[j], lo8[j]);
    long long o = (long long)node * 128 + sub * 8;
    *(uint4*)(g_Agh + o) = *(uint4*)hi8;
    *(uint4*)(g_Agl + o) = *(uint4*)lo8;
}

// ---------------- split-bf16 HMMA dual GEMM, cp.async pipelined -------------
// D[i,o] = sum_k A[i,k]*B[o,k], A = [agg | h] (K=256) pre-split bf16 hi/lo.
// 8 k-chunks of 32, 2-stage cp.async pipeline. Block 128x128, 8 warps 4x2.
#define KSTR 40      // bf16 elems per smem row (32 data + 8 pad): LDSM conflict-free
#define TILE_ELEMS (128 * KSTR)
// stage layout: [Ah, Al, Bh, Bl] per stage
#define SM_STAGE (4 * TILE_ELEMS)
#define SM_BYTES (2 * SM_STAGE * 2)

__global__ __launch_bounds__(256, 2)
void hmma_gemm_kernel(const __nv_bfloat16* __restrict__ Agh,  // agg hi [N,128]
                      const __nv_bfloat16* __restrict__ Agl,
                      const __nv_bfloat16* __restrict__ Hh,   // root hi [N,128]
                      const __nv_bfloat16* __restrict__ Hl,
                      const __nv_bfloat16* __restrict__ Bhi,  // [128,256]
                      const __nv_bfloat16* __restrict__ Blo,
                      const float* __restrict__ bias,
                      float* __restrict__ out,
                      __half* __restrict__ outx,              // fp16 copy (or null)
                      __nv_bfloat16* __restrict__ oh,         // bf16 hi copy (or null)
                      __nv_bfloat16* __restrict__ ol,         // bf16 lo copy (or null)
                      int n) {
    extern __shared__ __nv_bfloat16 sm[];
    uint32_t sbase = smem_u32(sm);

    int tid = threadIdx.x;
    int wid = tid >> 5;
    int lane = tid & 31;
    int wm = wid & 3;         // m tile (rows wm*32)
    int wn = wid >> 2;        // n half (cols wn*64)
    int g = lane >> 2;
    int tg = lane & 3;
    int rowBase = blockIdx.x * 128;
    int mrow = wm * 32;

    // cp.async roles: row = tid>>1; each thread loads 2 consecutive 16B segs.
    // even thread: row elements [0..15]; odd thread: elements [16..31].
    int lrow = tid >> 1;                        // 0..127
    int lelem = (tid & 1) * 16;                 // 0 or 16 (elements)
    int garow = rowBase + lrow;
    if (garow >= n) garow = n - 1;              // clamp (OOB rows never consumed)
    long long aoff = (long long)garow * 128 + lelem;
    uint32_t sArow = (uint32_t)((lrow * KSTR + lelem) * 2);   // bytes

    // ldmatrix per-lane byte offsets (stride KSTR)
    int laneRowA = (lane & 7) + ((lane >> 3) & 1) * 8;
    int laneKA   = (lane >> 4) * 8;
    uint32_t aOff0 = (uint32_t)(((mrow + laneRowA) * KSTR + laneKA) * 2);
    uint32_t aOff1 = (uint32_t)(((mrow + 16 + laneRowA) * KSTR + laneKA) * 2);
    int laneRowB = (lane & 7) + (lane >> 4) * 8;
    int laneKB   = ((lane >> 3) & 1) * 8;
    uint32_t bOff[4];
#pragma unroll
    for (int p = 0; p < 4; p++)
        bOff[p] = (uint32_t)(((wn * 64 + p * 16 + laneRowB) * KSTR + laneKB) * 2);

    float acc[2][8][4];
#pragma unroll
    for (int mt = 0; mt < 2; mt++)
#pragma unroll
        for (int nt = 0; nt < 8; nt++)
#pragma unroll
            for (int j = 0; j < 4; j++) acc[mt][nt][j] = 0.f;

    // ---- stage loader (fixed: consecutive segments, +8 elems / +16 bytes) ----
    auto load_stage = [&](int s, int buf) {
        uint32_t sb = sbase + (uint32_t)(buf * SM_STAGE * 2);
        const __nv_bfloat16* Ah = (s < 4) ? Agh : Hh;
        const __nv_bfloat16* Al = (s < 4) ? Agl : Hl;
        int kb = (s & 3) * 32;
        cpa16(sb + sArow,                        Ah + aoff + kb);
        cpa16(sb + sArow + 16,                   Ah + aoff + kb + 8);
        cpa16(sb + TILE_ELEMS * 2 + sArow,       Al + aoff + kb);
        cpa16(sb + TILE_ELEMS * 2 + sArow + 16,  Al + aoff + kb + 8);
        long long boff = (long long)lrow * 256 + s * 32 + lelem;
        cpa16(sb + TILE_ELEMS * 4 + sArow,       Bhi + boff);
        cpa16(sb + TILE_ELEMS * 4 + sArow + 16,  Bhi + boff + 8);
        cpa16(sb + TILE_ELEMS * 6 + sArow,       Blo + boff);
        cpa16(sb + TILE_ELEMS * 6 + sArow + 16,  Blo + boff + 8);
        cpa_commit();
    };

    load_stage(0, 0);

    for (int s = 0; s < 8; s++) {
        int buf = s & 1;
        if (s < 7) load_stage(s + 1, buf ^ 1);
        if (s < 7) cpa_wait<1>(); else cpa_wait<0>();
        __syncthreads();

        uint32_t sb = sbase + (uint32_t)(buf * SM_STAGE * 2);
        uint32_t suAh = sb;
        uint32_t suAl = sb + TILE_ELEMS * 2;
        uint32_t suBh = sb + TILE_ELEMS * 4;
        uint32_t suBl = sb + TILE_ELEMS * 6;

#pragma unroll
        for (int ks = 0; ks < 2; ks++) {
            uint32_t kbb = (uint32_t)(ks * 32);     // 16 elems * 2B
            uint32_t ah[2][4], al[2][4];
            ldsm4(ah[0], suAh + aOff0 + kbb);
            ldsm4(ah[1], suAh + aOff1 + kbb);
            ldsm4(al[0], suAl + aOff0 + kbb);
            ldsm4(al[1], suAl + aOff1 + kbb);
#pragma unroll
            for (int p = 0; p < 4; p++) {
                uint32_t bh[4], bl[4];
                ldsm4(bh, suBh + bOff[p] + kbb);
                ldsm4(bl, suBl + bOff[p] + kbb);
#pragma unroll
                for (int mt = 0; mt < 2; mt++) {
                    mma16816(acc[mt][2 * p],     ah[mt], bh);
                    mma16816(acc[mt][2 * p],     ah[mt], bl);
                    mma16816(acc[mt][2 * p],     al[mt], bh);
                    mma16816(acc[mt][2 * p + 1], ah[mt], bh + 2);
                    mma16816(acc[mt][2 * p + 1], ah[mt], bl + 2);
                    mma16816(acc[mt][2 * p + 1], al[mt], bh + 2);
                }
            }
        }
        __syncthreads();
    }

    // ---- epilogue: bias + relu; fp32 out + optional fp16 / bf16-split copies
#pragma unroll
    for (int mt = 0; mt < 2; mt++) {
        int gr0 = rowBase + mrow + mt * 16 + g;
        int gr1 = gr0 + 8;
#pragma unroll
        for (int nt = 0; nt < 8; nt++) {
            int col = wn * 64 + nt * 8 + tg * 2;
            float2 bb = *(const float2*)(bias + col);
#pragma unroll
            for (int half = 0; half < 2; half++) {
                int gr = half ? gr1 : gr0;
                if (gr >= n) continue;
                float vx = fmaxf(acc[mt][nt][2 * half]     + bb.x, 0.f);
                float vy = fmaxf(acc[mt][nt][2 * half + 1] + bb.y, 0.f);
                long long o = (long long)gr * 128 + col;
                *(float2*)(out + o) = make_float2(vx, vy);
                if (outx) *(__half2*)(outx + o) = __floats2half2_rn(vx, vy);
                if (oh) {
                    __nv_bfloat16 hx, lx, hy, ly;
                    bf16split(vx, hx, lx);
                    bf16split(vy, hy, ly);
                    __nv_bfloat162 ph; ph.x = hx; ph.y = hy;
                    __nv_bfloat162 pl; pl.x = lx; pl.y = ly;
                    *(__nv_bfloat162*)(oh + o) = ph;
                    *(__nv_bfloat162*)(ol + o) = pl;
                }
            }
        }
    }
}

// ---------------- launch ----------------
extern "C" void kernel_launch(void* const* d_in, const int* in_sizes, int n_in,
                              void* d_out, int out_size) {
    // ---- rank-based classification: emb > edge > x > 4x weights > 2x biases ----
    long long sz[32];
    int used[32];
    int m = n_in > 32 ? 32 : n_in;
    for (int i = 0; i < m; i++) { sz[i] = (long long)in_sizes[i]; used[i] = 0; }

    int iEmb = -1, iEdge = -1, iX = -1;
    for (int pass = 0; pass < 3; pass++) {
        long long best = -1; int bi = -1;
        for (int i = 0; i < m; i++)
            if (!used[i] && sz[i] > best) { best = sz[i]; bi = i; }
        used[bi] = 1;
        if (pass == 0) iEmb = bi; else if (pass == 1) iEdge = bi; else iX = bi;
    }
    long long wsz = -1;
    for (int i = 0; i < m; i++) if (!used[i] && sz[i] > wsz) wsz = sz[i];
    const float* Wlist[4] = {0, 0, 0, 0};
    const float* blist[2] = {0, 0};
    int nW = 0, nb = 0;
    for (int i = 0; i < m; i++) {
        if (used[i]) continue;
        if (sz[i] == wsz && nW < 4) Wlist[nW++] = (const float*)d_in[i];
        else if (nb < 2)            blist[nb++] = (const float*)d_in[i];
    }

    const float* emb = (const float*)d_in[iEmb];
    const int*   ei  = (const int*)d_in[iEdge];
    const int*   x   = (const int*)d_in[iX];

    int bytesMode = (sz[iEmb] > 300000000LL) ? 1 : 0;
    long long div = bytesMode ? 4 : 1;
    long long embRows = sz[iEmb] / div / 128;
    long long N_ll = (long long)out_size / (128 * div);
    if (N_ll < 1) N_ll = 1;
    if (N_ll > NN) N_ll = NN;
    int N = (int)N_ll;

    long long eiW = sz[iEdge] / div;
    long long xW  = sz[iX]   / div;
    int elemMode = bytesMode ? 0 : 1;

    long long Emax = eiW / 2; if (Emax > EE) Emax = EE; if (Emax < 1) Emax = 1;

    const float* W1l = Wlist[0];
    const float* W1r = Wlist[1];
    const float* W2l = Wlist[2];
    const float* W2r = Wlist[3];
    const float* b1  = blist[0];
    const float* b2  = blist[1];
    float* out = (float*)d_out;

    // resolve true device addresses of __device__ globals (ATS trap otherwise)
    __half *p_hx = nullptr, *p_h2x = nullptr;
    __nv_bfloat16 *p_Hh = nullptr, *p_Hl = nullptr, *p_H2h = nullptr, *p_H2l = nullptr;
    __nv_bfloat16 *p_Agh = nullptr, *p_Agl = nullptr;
    __nv_bfloat16 *p_bhi1 = nullptr, *p_blo1 = nullptr, *p_bhi2 = nullptr, *p_blo2 = nullptr;
    cudaGetSymbolAddress((void**)&p_hx,   g_hx);
    cudaGetSymbolAddress((void**)&p_h2x,  g_h2x);
    cudaGetSymbolAddress((void**)&p_Hh,   g_Hh);
    cudaGetSymbolAddress((void**)&p_Hl,   g_Hl);
    cudaGetSymbolAddress((void**)&p_H2h,  g_H2h);
    cudaGetSymbolAddress((void**)&p_H2l,  g_H2l);
    cudaGetSymbolAddress((void**)&p_Agh,  g_Agh);
    cudaGetSymbolAddress((void**)&p_Agl,  g_Agl);
    cudaGetSymbolAddress((void**)&p_bhi1, g_Bhi1);
    cudaGetSymbolAddress((void**)&p_blo1, g_Blo1);
    cudaGetSymbolAddress((void**)&p_bhi2, g_Bhi2);
    cudaGetSymbolAddress((void**)&p_blo2, g_Blo2);

    cudaFuncSetAttribute(hmma_gemm_kernel,
                         cudaFuncAttributeMaxDynamicSharedMemorySize, SM_BYTES);

    int nBlk = (N + 255) / 256;
    int edgeBlocks = (int)((Emax + 255) / 256);
    int gpBlocks = (N * 32 + 2 * 128 * 256 + 255) / 256;

    // ---- pipeline (6 launches) ----
    init_kernel<<<nBlk, 256>>>(ei, eiW, x, xW, elemMode, N);
    build_kernel<<<edgeBlocks + gpBlocks, 256>>>(ei, x, emb, N, embRows,
                                                 W1l, W1r, W2l, W2r, edgeBlocks);

    int aggBlocks = (N * 16 + 255) / 256;
    int gemmBlocks = (N + 127) / 128;

    aggregate_kernel<<<aggBlocks, 256>>>(p_hx, ei, N);
    // layer-1 fp32 output lands in d_out as scratch; layer-2 overwrites it.
    hmma_gemm_kernel<<<gemmBlocks, 256, SM_BYTES>>>(p_Agh, p_Agl, p_Hh, p_Hl,
                                                    p_bhi1, p_blo1, b1,
                                                    out, p_h2x, p_H2h, p_H2l, N);

    aggregate_kernel<<<aggBlocks, 256>>>(p_h2x, ei, N);
    hmma_gemm_kernel<<<gemmBlocks, 256, SM_BYTES>>>(p_Agh, p_Agl, p_H2h, p_H2l,
                                                    p_bhi2, p_blo2, b2,
                                                    out, (__half*)nullptr,
                                                    (__nv_bfloat16*)nullptr,
                                                    (__nv_bfloat16*)nullptr, N);
}